// round 14
// baseline (speedup 1.0000x reference)
#include <cuda_runtime.h>
#include <cuda_bf16.h>
#include <math.h>

#define NN 30000
#define EE 480000
#define DD 128
#define CAP 96          // padded CSR capacity (Poisson(16): P(deg>96) ~ 1e-40)
#define NPB 4           // nodes per agg block (2 warps per node); 30000/4 = 7500 exact

// ---------------- static device scratch (zero-initialized at module load) ----------------
__device__ float g_z[NN * DD];
__device__ float g_hout[NN * DD];
__device__ int   g_cursor[NN];          // self-cleaned by agg each invocation
__device__ int   g_srcs[NN * CAP];
__device__ float g_stats[2 * DD];       // zeroed by build_kernel block 0 each invocation

__device__ __forceinline__ float ex2(float x) {
    float r; asm("ex2.approx.f32 %0, %1;" : "=f"(r) : "f"(x)); return r;
}

// ---------------- GEMM (byte-exact measured-good 100.4 version) ----------------
__global__ void gemm_kernel(const float* __restrict__ h, const float* __restrict__ W) {
    __shared__ float As[64][33];
    __shared__ float Bs[128][33];
    int t = threadIdx.x;
    int tx = t & 31;
    int ty = t >> 5;
    int rowBase = blockIdx.x * 64;

    float acc[8][4];
#pragma unroll
    for (int i = 0; i < 8; i++)
#pragma unroll
        for (int j = 0; j < 4; j++) acc[i][j] = 0.f;

    for (int kc = 0; kc < DD; kc += 32) {
#pragma unroll
        for (int l = 0; l < 8; l++) {
            int lin = t + 256 * l;
            int r = lin >> 5, kk = lin & 31;
            int row = rowBase + r;
            As[r][kk] = (row < NN) ? h[row * DD + kc + kk] : 0.f;
        }
#pragma unroll
        for (int l = 0; l < 16; l++) {
            int lin = t + 256 * l;
            int r = lin >> 5, kk = lin & 31;
            Bs[r][kk] = W[r * DD + kc + kk];
        }
        __syncthreads();
#pragma unroll
        for (int kk = 0; kk < 32; kk++) {
            float a[8], b[4];
#pragma unroll
            for (int i = 0; i < 8; i++) a[i] = As[ty + 8 * i][kk];
#pragma unroll
            for (int j = 0; j < 4; j++) b[j] = Bs[tx + 32 * j][kk];
#pragma unroll
            for (int i = 0; i < 8; i++)
#pragma unroll
                for (int j = 0; j < 4; j++) acc[i][j] = fmaf(a[i], b[j], acc[i][j]);
        }
        __syncthreads();
    }
#pragma unroll
    for (int i = 0; i < 8; i++) {
        int row = rowBase + ty + 8 * i;
        if (row < NN) {
#pragma unroll
            for (int j = 0; j < 4; j++) g_z[row * DD + tx + 32 * j] = acc[i][j];
        }
    }
}

// ---------------- build padded CSR (+ zero BN stats for this invocation) ----------------
__global__ void build_kernel(const int* __restrict__ src, const int* __restrict__ dst) {
    if (blockIdx.x == 0 && threadIdx.x < 2 * DD) g_stats[threadIdx.x] = 0.f;
    int e = blockIdx.x * 256 + threadIdx.x;
    if (e < EE) {
        int d = dst[e];
        int pos = atomicAdd(&g_cursor[d], 1);
        if (pos < CAP) g_srcs[d * CAP + pos] = src[e];
    }
}

// ---------------- agg: 2 warps per node, float2 per lane (64 ch/warp), fused BN stats ----------------
// Low register pressure -> 8 blocks/SM -> high occupancy; 60000 warps cover L2 latency.
__global__ void __launch_bounds__(256) agg_kernel(const float* __restrict__ snorm) {
    __shared__ int   ssrc[NPB][CAP];
    __shared__ float shv[NPB][DD];

    int warp = threadIdx.x >> 5;
    int lane = threadIdx.x & 31;
    int n    = warp >> 1;                 // local node 0..3
    int half = warp & 1;                  // channel half
    int d = blockIdx.x * NPB + n;

    int deg = g_cursor[d];
    if (deg > CAP) deg = CAP;

    // cooperative index load: 64 threads per node, striped by t64
    int t64 = threadIdx.x & 63;
    for (int i = t64; i < deg; i += 64) ssrc[n][i] = g_srcs[d * CAP + i];

    int c0 = half * 64 + lane * 2;        // this lane's channel pair
    const float L2E = 1.44269504f;
    float2 zd = *(const float2*)(g_z + d * DD + c0);
    float2 ze = make_float2(zd.x * L2E, zd.y * L2E);
    float sn = snorm[d];
    __syncthreads();

    // Self-clean AFTER the sync: both warps of this node have read deg by now,
    // and no other block touches g_cursor[d]. (Resetting before the sync raced
    // with the partner warp's read and left ssrc[32..63] uninitialized.)
    if (half == 0 && lane == 0) g_cursor[d] = 0;

    float2 den  = make_float2(0.f, 0.f), acc  = den;
    float2 den2 = den, acc2 = den;

    int i = 0;
    for (; i + 2 <= deg; i += 2) {
        int s0 = ssrc[n][i];
        int s1 = ssrc[n][i + 1];
        float2 a = *(const float2*)(g_z + s0 * DD + c0);
        float2 b = *(const float2*)(g_z + s1 * DD + c0);
        float w0, w1;
        w0 = ex2(a.x * ze.x); den.x  += w0; acc.x  = fmaf(w0, a.x, acc.x);
        w1 = ex2(b.x * ze.x); den2.x += w1; acc2.x = fmaf(w1, b.x, acc2.x);
        w0 = ex2(a.y * ze.y); den.y  += w0; acc.y  = fmaf(w0, a.y, acc.y);
        w1 = ex2(b.y * ze.y); den2.y += w1; acc2.y = fmaf(w1, b.y, acc2.y);
    }
    if (i < deg) {
        int s0 = ssrc[n][i];
        float2 a = *(const float2*)(g_z + s0 * DD + c0);
        float w0;
        w0 = ex2(a.x * ze.x); den.x += w0; acc.x = fmaf(w0, a.x, acc.x);
        w0 = ex2(a.y * ze.y); den.y += w0; acc.y = fmaf(w0, a.y, acc.y);
    }
    den.x += den2.x; den.y += den2.y;
    acc.x += acc2.x; acc.y += acc2.y;

    float2 hv;
    hv.x = (den.x > 0.f) ? (acc.x / den.x) * sn : 0.f;
    hv.y = (den.y > 0.f) ? (acc.y / den.y) * sn : 0.f;

    *(float2*)(g_hout + d * DD + c0) = hv;
    *(float2*)(&shv[n][c0]) = hv;
    __syncthreads();

    // BN partial stats: threads 0..127 sum channel c; 128..255 sumsq channel c-128
    int tid = threadIdx.x;
    int c = tid & (DD - 1);
    if (tid < DD) {
        float s = 0.f;
#pragma unroll
        for (int ww = 0; ww < NPB; ww++) s += shv[ww][c];
        atomicAdd(&g_stats[c], s);
    } else {
        float s2 = 0.f;
#pragma unroll
        for (int ww = 0; ww < NPB; ww++) { float v = shv[ww][c]; s2 = fmaf(v, v, s2); }
        atomicAdd(&g_stats[DD + c], s2);
    }
}

// ---------------- BN apply + ELU (folds stats inline; measured-neutral fusion) ----------------
__global__ void __launch_bounds__(256) apply_kernel(const float* __restrict__ gamma,
                                                    const float* __restrict__ beta,
                                                    float* __restrict__ out) {
    __shared__ float ssc[DD], sbi[DD];
    int t = threadIdx.x;
    if (t < DD) {
        const float invN = 1.f / (float)NN;
        float mu = g_stats[t] * invN;
        float var = g_stats[DD + t] * invN - mu * mu;
        float sc = rsqrtf(var + 1e-5f) * gamma[t];
        ssc[t] = sc;
        sbi[t] = beta[t] - mu * sc;
    }
    __syncthreads();

    int q = blockIdx.x * 256 + t;
    if (q >= NN * DD / 4) return;
    int c4 = (q & 31) * 4;
    float4 hv = *(const float4*)&g_hout[q * 4];
    float4 o;
    float v;
    v = fmaf(hv.x, ssc[c4 + 0], sbi[c4 + 0]); o.x = (v > 0.f) ? v : expm1f(v);
    v = fmaf(hv.y, ssc[c4 + 1], sbi[c4 + 1]); o.y = (v > 0.f) ? v : expm1f(v);
    v = fmaf(hv.z, ssc[c4 + 2], sbi[c4 + 2]); o.z = (v > 0.f) ? v : expm1f(v);
    v = fmaf(hv.w, ssc[c4 + 3], sbi[c4 + 3]); o.w = (v > 0.f) ? v : expm1f(v);
    *(float4*)&out[q * 4] = o;
}

// ---------------- launch ----------------
extern "C" void kernel_launch(void* const* d_in, const int* in_sizes, int n_in,
                              void* d_out, int out_size) {
    const float* h      = (const float*)d_in[0];
    const float* snorm  = (const float*)d_in[1];
    const float* W      = (const float*)d_in[2];
    const float* gamma  = (const float*)d_in[3];
    const float* beta   = (const float*)d_in[4];
    const int*   src    = (const int*)d_in[5];
    const int*   dst    = (const int*)d_in[6];
    float* out = (float*)d_out;

    build_kernel<<<(EE + 255) / 256, 256>>>(src, dst);
    gemm_kernel<<<(NN + 63) / 64, 256>>>(h, W);
    agg_kernel<<<NN / NPB, 256>>>(snorm);
    apply_kernel<<<(NN * DD / 4 + 255) / 256, 256>>>(gamma, beta, out);
}